// round 9
// baseline (speedup 1.0000x reference)
#include <cuda_runtime.h>
#include <cstdint>

#define TT 512      // time steps
#define NB 512      // batch
#define CC 80       // classes
#define SS 128      // max target len
#define LL 257      // extended lattice = 2*SS+1
#define WPB 4       // batch elems per block
#define NEB 8       // em ring depth (rows)
#define NBC (NB*CC) // row stride in floats

static __device__ __forceinline__ unsigned smem_u32(const void* p) {
    return (unsigned)__cvta_generic_to_shared(p);
}
// exact power of two 2^e, exponent clamped to normal range
static __device__ __forceinline__ float exp2c(int e) {
    e = max(-126, min(127, e));
    return __int_as_float((e + 127) << 23);
}
static __device__ __forceinline__ int ld_acq(unsigned a) {
    int v;
    asm volatile("ld.acquire.cta.shared.b32 %0, [%1];" : "=r"(v) : "r"(a) : "memory");
    return v;
}
static __device__ __forceinline__ void st_rel(unsigned a, int v) {
    asm volatile("st.release.cta.shared.b32 [%0], %1;" :: "r"(a), "r"(v) : "memory");
}

struct WState {
    float a[9];     // alpha cells (lattice s = lane*9 + j)
    float sk[9];    // skip-transition multiplier (0/1)
    int   co[9];    // emission byte offset = class*4
    float p8r, p7r; // pre-rescale boundary alphas shfl'd from lane-1
    int   elane;    // per-lane exponent: true alpha = a * 2^elane
    int   eprev;    // lane-1's elane at shfl time
    bool  empty;    // lane has no probability mass yet
};

template <bool RESC>
static __device__ __forceinline__ void ctc_step(
    WState& S, int tcur, int lane, float (&emW)[NEB][84])
{
    // emission gathers for row tcur (produced by partner warp)
    const char* emc = (const char*)&emW[tcur & (NEB - 1)][0];
    float g[9];
#pragma unroll
    for (int j = 0; j < 9; j++)
        g[j] = *(const float*)(emc + S.co[j]);

    // exponent alignment with left neighbor
    int de = S.eprev - S.elane;
    if (S.empty) { S.elane = S.eprev; de = 0; }        // alpha==0: adopt, no mults
    else if (de > 100) {                               // ~never taken
        if (de > 252) {
#pragma unroll
            for (int j = 0; j < 9; j++) S.a[j] = 0.f;
        } else {
            float r1 = exp2c(-(de >> 1)), r2 = exp2c(-(de - (de >> 1)));
#pragma unroll
            for (int j = 0; j < 9; j++) S.a[j] = (S.a[j] * r1) * r2;
        }
        S.elane += de; de = 0;
    }
    float f  = exp2c(de);
    float p8 = S.p8r * f, p7 = S.p7r * f;

    // cell updates, descending so in-place reads see old values
#pragma unroll
    for (int j = 8; j >= 2; j--) {
        float tv = S.a[j] + S.a[j - 1];
        tv = fmaf(S.a[j - 2], S.sk[j], tv);
        S.a[j] = tv * g[j];
    }
    { float tv = S.a[1] + S.a[0]; tv = fmaf(p8, S.sk[1], tv); S.a[1] = tv * g[1]; }
    { float tv = S.a[0] + p8;     tv = fmaf(p7, S.sk[0], tv); S.a[0] = tv * g[0]; }

    if (p8 > 0.f) S.empty = false;   // mass injected from the left

    // early shfl for NEXT step (pre-rescale values + current exponent)
    S.p8r   = __shfl_up_sync(0xffffffffu, S.a[8], 1);
    S.p7r   = __shfl_up_sync(0xffffffffu, S.a[7], 1);
    S.eprev = __shfl_up_sync(0xffffffffu, S.elane, 1);
    if (lane == 0) { S.p8r = 0.f; S.p7r = 0.f; S.eprev = S.elane; }

    if (RESC) {   // per-lane power-of-2 renormalization (every 2nd step)
        float m = fmaxf(fmaxf(fmaxf(S.a[0], S.a[1]), fmaxf(S.a[2], S.a[3])),
                        fmaxf(fmaxf(S.a[4], S.a[5]),
                              fmaxf(fmaxf(S.a[6], S.a[7]), S.a[8])));
        if (m > 0.f) {
            int e = ((__float_as_int(m) >> 23) & 255) - 127;
            float sc = exp2c(-e);
#pragma unroll
            for (int j = 0; j < 9; j++) S.a[j] *= sc;
            S.elane += e;
            S.empty = false;
        } else {
            S.empty = true;
        }
    }
}

__global__ __launch_bounds__(WPB * 64)
void ctc_kernel(const float* __restrict__ lp,   // (T, N, C)
                const int*   __restrict__ tgt,  // (N, S)
                const int*   __restrict__ ilen, // (N,)
                const int*   __restrict__ tlen, // (N,)
                float*       __restrict__ out,  // (N,)
                int nb)
{
    __shared__ __align__(16) float em[WPB][NEB][84]; // em ring: exp'd prob rows (+pad slot 80)
    __shared__ int   flg[WPB][32];                   // [0]=rows produced, [16]=consumer progress
    __shared__ float dmp[WPB][292];                  // finalize dump
    __shared__ int   ed[WPB][32];                    // per-lane exponents at finalize

    const int tid  = threadIdx.x;
    const int lane = tid & 31;
    const int wid  = tid >> 5;
    const int w    = wid & (WPB - 1);
    const bool producer = wid >= WPB;
    const int n    = blockIdx.x * WPB + w;

    if (!producer && n < nb) {
        if (lane == 0) { flg[w][0] = 0; flg[w][16] = 0; }
        if (lane < NEB) em[w][lane][80] = 0.f;       // pad class -> prob 0
    }
    __syncthreads();
    if (n >= nb) return;

    const int Tn = ilen[n];

    if (producer) {
        // ================= producer warp: stream + exp-convert rows =================
        const float* gsrc = lp + (size_t)n * CC + lane * 4;
        const unsigned fa = smem_u32(&flg[w][0]);
        volatile int* cprog = &flg[w][16];

        float4 q[4];
#pragma unroll
        for (int i = 0; i < 4; i++)
            q[i] = (lane < 20) ? *(const float4*)(gsrc + (size_t)i * NBC)
                               : make_float4(0.f, 0.f, 0.f, 0.f);

        int pt = 0, cc = 0;
        while (pt < Tn) {
            // backpressure: produce rows [pt, pt+3] only if pt+3 <= cc+9
            while (pt + 3 > cc + 9) cc = *cprog;
#pragma unroll
            for (int qi = 0; qi < 4; qi++) {
                if (pt < Tn) {
                    if (lane < 20) {
                        float4 p;
                        p.x = __expf(q[qi].x); p.y = __expf(q[qi].y);
                        p.z = __expf(q[qi].z); p.w = __expf(q[qi].w);
                        *(float4*)&em[w][pt & (NEB - 1)][lane * 4] = p;
                    }
                    if (lane < 20 && pt + 4 < Tn)
                        q[qi] = *(const float4*)(gsrc + (size_t)(pt + 4) * NBC);
                    pt++;
                }
            }
            __syncwarp();
            if (lane == 0) st_rel(fa, pt);           // publish rows produced
        }
        return;
    }

    // ================= consumer warp: the CTC recurrence =================
    float (&emW)[NEB][84] = em[w];
    const unsigned fa = smem_u32(&flg[w][0]);
    volatile int* cprog = &flg[w][16];
    const int tl = tlen[n];

    WState S;
    const int* trow = tgt + (size_t)n * SS;
#pragma unroll
    for (int j = 0; j < 9; j++) {
        int s = lane * 9 + j;
        S.a[j] = 0.f;
        if (s >= LL)            { S.co[j] = 80 * 4; S.sk[j] = 0.f; }
        else if ((s & 1) == 0)  { S.co[j] = 0;      S.sk[j] = 0.f; }   // blank
        else {
            int k = s >> 1;
            int c = trow[k];
            S.co[j] = c * 4;
            S.sk[j] = (k >= 1 && trow[k - 1] != c) ? 1.f : 0.f;
        }
    }

    int fcache = 0;
    while (fcache < 1) fcache = ld_acq(fa);          // wait for row 0

    // alpha at t=0: only lattice positions 0 (blank) and 1 (first label)
    if (lane == 0) {
        S.a[0] = *(const float*)((const char*)&emW[0][0] + 0);
        S.a[1] = *(const float*)((const char*)&emW[0][0] + S.co[1]);
    }
    S.elane = 0;
    S.empty = (lane != 0);

    S.p8r   = __shfl_up_sync(0xffffffffu, S.a[8], 1);
    S.p7r   = __shfl_up_sync(0xffffffffu, S.a[7], 1);
    S.eprev = __shfl_up_sync(0xffffffffu, S.elane, 1);
    if (lane == 0) { S.p8r = 0.f; S.p7r = 0.f; S.eprev = S.elane; }

    // ---- main loop: steps 1 .. Tn-1, unrolled by 2 ----
    int t = 1;
    for (; t + 1 < Tn; t += 2) {
        if ((t & 3) == 1) *cprog = t;                // publish progress (every 4 steps)
        if (fcache < t + 2)
            do { fcache = ld_acq(fa); } while (fcache < t + 2);
        ctc_step<false>(S, t,     lane, emW);
        ctc_step<true >(S, t + 1, lane, emW);
    }
    if (t < Tn) {
        *cprog = t;
        if (fcache < t + 1)
            do { fcache = ld_acq(fa); } while (fcache < t + 1);
        ctc_step<true>(S, t, lane, emW);
    }
    *cprog = Tn + 8;                                  // release any waiting producer

    // ---- finalize: combine alpha[2*tl] + alpha[2*tl-1] with per-lane exponents ----
#pragma unroll
    for (int j = 0; j < 9; j++)
        dmp[w][lane * 9 + j] = S.a[j];
    ed[w][lane] = S.elane;
    __syncwarp();
    if (lane == 0) {
        int s1 = 2 * tl, s2 = 2 * tl - 1;
        float va = dmp[w][s1]; int ea = ed[w][s1 / 9];
        float vb = dmp[w][s2]; int eb = ed[w][s2 / 9];
        int emax = max(ea, eb);
        float v = va * exp2c(ea - emax) + vb * exp2c(eb - emax);
        float loss = -((__log2f(v) + (float)emax) * 0.69314718055994530942f);
        if (!isfinite(loss) || !(loss < 1e10f)) loss = 0.f;  // zero_infinity
        out[n] = loss;
    }
}

extern "C" void kernel_launch(void* const* d_in, const int* in_sizes, int n_in,
                              void* d_out, int out_size) {
    const float* lp   = (const float*)d_in[0];
    const int*   tgt  = (const int*)d_in[1];
    const int*   ilen = (const int*)d_in[2];
    const int*   tlen = (const int*)d_in[3];
    float*       out  = (float*)d_out;
    int nb = out_size;                 // N
    int blocks = (nb + WPB - 1) / WPB; // 128
    ctc_kernel<<<blocks, WPB * 64>>>(lp, tgt, ilen, tlen, out, nb);
}

// round 10
// speedup vs baseline: 1.1847x; 1.1847x over previous
#include <cuda_runtime.h>
#include <cstdint>

#define TT 512      // time steps
#define NB 512      // batch
#define CC 80       // classes
#define SS 128      // max target len
#define LL 257      // extended lattice = 2*SS+1
#define WPB 4       // warps (batch elems) per block
#define RD 8        // raw ring depth (rows)
#define NEB 4       // em ring depth (rows)
#define NBC (NB*CC) // row stride in floats

static __device__ __forceinline__ unsigned smem_u32(const void* p) {
    return (unsigned)__cvta_generic_to_shared(p);
}
static __device__ __forceinline__ void cp16(unsigned dst, const float* src) {
    asm volatile("cp.async.cg.shared.global [%0], [%1], 16;\n"
                 :: "r"(dst), "l"(__cvta_generic_to_global(src)) : "memory");
}
static __device__ __forceinline__ void cp_commit() {
    asm volatile("cp.async.commit_group;\n" ::: "memory");
}
template <int N> static __device__ __forceinline__ void cp_wait() {
    asm volatile("cp.async.wait_group %0;\n" :: "n"(N) : "memory");
}
// exact power of two 2^e, exponent clamped to normal range
static __device__ __forceinline__ float exp2c(int e) {
    e = max(-126, min(127, e));
    return __int_as_float((e + 127) << 23);
}

struct WState {
    float a[9];     // alpha cells (lattice s = lane*9 + j)
    float sk[9];    // skip-transition multiplier (0/1)
    int   co[9];    // emission byte offset = class*4
    float p8r, p7r; // pre-rescale boundary alphas shfl'd from lane-1
    int   elane;    // per-lane exponent: true alpha = a * 2^elane
    int   eprev;    // lane-1's elane (refreshed once per superstep)
    bool  empty;    // lane has no probability mass yet (refreshed at rescale)
};

// One recurrence step. RESC: renormalize. SHFL_E: refresh eprev this step.
template <bool RESC, bool SHFL_E>
static __device__ __forceinline__ void ctc_step(
    WState& S, int lane, const float* emrow)
{
    const char* emc = (const char*)emrow;
    float g[9];
#pragma unroll
    for (int j = 0; j < 9; j++)
        g[j] = *(const float*)(emc + S.co[j]);

    // exponent alignment with left neighbor
    int de = S.eprev - S.elane;
    if (S.empty) { S.elane = S.eprev; de = 0; }        // alpha==0: adopt (idempotent)
    else if (de > 100) {                               // ~never taken
        if (de > 252) {
#pragma unroll
            for (int j = 0; j < 9; j++) S.a[j] = 0.f;
        } else {
            float r1 = exp2c(-(de >> 1)), r2 = exp2c(-(de - (de >> 1)));
#pragma unroll
            for (int j = 0; j < 9; j++) S.a[j] = (S.a[j] * r1) * r2;
        }
        S.elane += de; de = 0;
    }
    float f  = exp2c(de);
    float p8 = S.p8r * f, p7 = S.p7r * f;

    // cell updates, descending so in-place reads see old values
#pragma unroll
    for (int j = 8; j >= 2; j--) {
        float tv = S.a[j] + S.a[j - 1];
        tv = fmaf(S.a[j - 2], S.sk[j], tv);
        S.a[j] = tv * g[j];
    }
    { float tv = S.a[1] + S.a[0]; tv = fmaf(p8, S.sk[1], tv); S.a[1] = tv * g[1]; }
    { float tv = S.a[0] + p8;     tv = fmaf(p7, S.sk[0], tv); S.a[0] = tv * g[0]; }

    // early shfl for NEXT step (pre-rescale values; exponent pairs stay consistent)
    S.p8r = __shfl_up_sync(0xffffffffu, S.a[8], 1);
    S.p7r = __shfl_up_sync(0xffffffffu, S.a[7], 1);
    if (SHFL_E) {
        S.eprev = __shfl_up_sync(0xffffffffu, S.elane, 1);
        if (lane == 0) S.eprev = S.elane;
    }
    if (lane == 0) { S.p8r = 0.f; S.p7r = 0.f; }

    if (RESC) {   // per-lane power-of-2 renormalization (every 2nd step)
        float m = fmaxf(fmaxf(fmaxf(S.a[0], S.a[1]), fmaxf(S.a[2], S.a[3])),
                        fmaxf(fmaxf(S.a[4], S.a[5]),
                              fmaxf(fmaxf(S.a[6], S.a[7]), S.a[8])));
        if (m > 0.f) {
            int e = ((__float_as_int(m) >> 23) & 255) - 127;
            float sc = exp2c(-e);
#pragma unroll
            for (int j = 0; j < 9; j++) S.a[j] *= sc;
            S.elane += e;
            S.empty = false;
        } else {
            S.empty = true;
        }
    }
}

static __device__ __forceinline__ float4 exp4(float4 r) {
    float4 p;
    p.x = __expf(r.x); p.y = __expf(r.y); p.z = __expf(r.z); p.w = __expf(r.w);
    return p;
}

__global__ __launch_bounds__(WPB * 32)
void ctc_kernel(const float* __restrict__ lp,   // (T, N, C)
                const int*   __restrict__ tgt,  // (N, S)
                const int*   __restrict__ ilen, // (N,)
                const int*   __restrict__ tlen, // (N,)
                float*       __restrict__ out,  // (N,)
                int nb)
{
    __shared__ __align__(16) float raw[WPB][RD][CC];  // cp.async ring of raw rows
    __shared__ __align__(16) float em[WPB][NEB][84];  // em ring: exp'd rows (+pad slot 80)
    __shared__ int ed[WPB][32];                       // per-lane exponents at finalize

    const int lane = threadIdx.x & 31;
    const int w    = threadIdx.x >> 5;
    const int n    = blockIdx.x * WPB + w;
    if (n >= nb) return;

    float (&rawW)[RD][CC]  = raw[w];
    float (&emW)[NEB][84]  = em[w];

    const int Tn = ilen[n];
    const int tl = tlen[n];

    if (lane < NEB) emW[lane][80] = 0.f;   // pad class -> prob 0

    WState S;
    const int* trow = tgt + (size_t)n * SS;
#pragma unroll
    for (int j = 0; j < 9; j++) {
        int s = lane * 9 + j;
        S.a[j] = 0.f;
        if (s >= LL)            { S.co[j] = 80 * 4; S.sk[j] = 0.f; }
        else if ((s & 1) == 0)  { S.co[j] = 0;      S.sk[j] = 0.f; }   // blank
        else {
            int k = s >> 1;
            int c = trow[k];
            S.co[j] = c * 4;
            S.sk[j] = (k >= 1 && trow[k - 1] != c) ? 1.f : 0.f;
        }
    }

    const float* gbase = lp + (size_t)n * CC;

    // ---- prologue: rows 0..8 in 5 groups: (0,1)(2,3)(4,5)(6,7)(8) ----
#pragma unroll
    for (int gpair = 0; gpair < 4; gpair++) {
        if (lane < 20) {
            cp16(smem_u32(&rawW[2 * gpair][lane * 4]),
                 gbase + (size_t)(2 * gpair) * NBC + lane * 4);
            cp16(smem_u32(&rawW[2 * gpair + 1][lane * 4]),
                 gbase + (size_t)(2 * gpair + 1) * NBC + lane * 4);
        }
        cp_commit();
    }
    if (lane < 20)
        cp16(smem_u32(&rawW[8 & (RD - 1)][lane * 4]),
             gbase + (size_t)8 * NBC + lane * 4);
    cp_commit();

    cp_wait<3>();   // rows 0..3 landed
    __syncwarp();
    if (lane < 20) {    // convert rows 0,1,2 -> em 0,1,2
        *(float4*)&emW[0][lane * 4] = exp4(*(const float4*)&rawW[0][lane * 4]);
        *(float4*)&emW[1][lane * 4] = exp4(*(const float4*)&rawW[1][lane * 4]);
        *(float4*)&emW[2][lane * 4] = exp4(*(const float4*)&rawW[2][lane * 4]);
    }
    __syncwarp();

    // alpha at t=0: only lattice positions 0 (blank) and 1 (first label)
    if (lane == 0) {
        S.a[0] = *(const float*)((const char*)&emW[0][0] + 0);
        S.a[1] = *(const float*)((const char*)&emW[0][0] + S.co[1]);
    }
    S.elane = 0;
    S.empty = (lane != 0);

    S.p8r   = __shfl_up_sync(0xffffffffu, S.a[8], 1);
    S.p7r   = __shfl_up_sync(0xffffffffu, S.a[7], 1);
    S.eprev = __shfl_up_sync(0xffffffffu, S.elane, 1);
    if (lane == 0) { S.p8r = 0.f; S.p7r = 0.f; S.eprev = S.elane; }

    // ---- main loop: supersteps (t, t+1) ----
    int t = 1;
    for (; t + 1 < Tn; t += 2) {
        cp_wait<2>();   // raw rows t+2, t+3 landed (>=3 supersteps of slack)

        // start long-latency convert loads first
        float4 ra = make_float4(0.f, 0.f, 0.f, 0.f), rb = ra;
        if (lane < 20) {
            ra = *(const float4*)&rawW[(t + 2) & (RD - 1)][lane * 4];
            rb = *(const float4*)&rawW[(t + 3) & (RD - 1)][lane * 4];
        }

        ctc_step<false, true >(S, lane, &emW[t & (NEB - 1)][0]);
        ctc_step<true,  false>(S, lane, &emW[(t + 1) & (NEB - 1)][0]);

        // exp-convert rows t+2, t+3 into em ring (consumed next superstep)
        if (lane < 20) {
            *(float4*)&emW[(t + 2) & (NEB - 1)][lane * 4] = exp4(ra);
            *(float4*)&emW[(t + 3) & (NEB - 1)][lane * 4] = exp4(rb);
        }

        // prefetch rows t+8, t+9 as one group (always commit to keep accounting)
        if (lane < 20) {
            if (t + 8 < TT)
                cp16(smem_u32(&rawW[(t + 8) & (RD - 1)][lane * 4]),
                     gbase + (size_t)(t + 8) * NBC + lane * 4);
            if (t + 9 < TT)
                cp16(smem_u32(&rawW[(t + 9) & (RD - 1)][lane * 4]),
                     gbase + (size_t)(t + 9) * NBC + lane * 4);
        }
        cp_commit();
        __syncwarp();
    }
    if (t < Tn)   // odd tail step (em row t already converted)
        ctc_step<true, true>(S, lane, &emW[t & (NEB - 1)][0]);

    // ---- finalize: combine alpha[2*tl] + alpha[2*tl-1] with per-lane exponents ----
    cp_wait<0>();     // drain all cp.async before reusing raw as scratch
    __syncwarp();
    float* dump = &rawW[0][0];   // 288 floats fit in the 640-float ring
#pragma unroll
    for (int j = 0; j < 9; j++)
        dump[lane * 9 + j] = S.a[j];
    ed[w][lane] = S.elane;
    __syncwarp();
    if (lane == 0) {
        int s1 = 2 * tl, s2 = 2 * tl - 1;
        float va = dump[s1]; int ea = ed[w][s1 / 9];
        float vb = dump[s2]; int eb = ed[w][s2 / 9];
        int emax = max(ea, eb);
        float v = va * exp2c(ea - emax) + vb * exp2c(eb - emax);
        float loss = -((__log2f(v) + (float)emax) * 0.69314718055994530942f);
        if (!isfinite(loss) || !(loss < 1e10f)) loss = 0.f;  // zero_infinity
        out[n] = loss;
    }
}

extern "C" void kernel_launch(void* const* d_in, const int* in_sizes, int n_in,
                              void* d_out, int out_size) {
    const float* lp   = (const float*)d_in[0];
    const int*   tgt  = (const int*)d_in[1];
    const int*   ilen = (const int*)d_in[2];
    const int*   tlen = (const int*)d_in[3];
    float*       out  = (float*)d_out;
    int nb = out_size;                 // N
    int blocks = (nb + WPB - 1) / WPB; // 128
    ctc_kernel<<<blocks, WPB * 32>>>(lp, tgt, ilen, tlen, out, nb);
}

// round 12
// speedup vs baseline: 1.3712x; 1.1575x over previous
#include <cuda_runtime.h>
#include <cstdint>

#define TT 512      // time steps
#define NB 512      // batch
#define CC 80       // classes
#define SS 128      // max target len
#define LL 257      // extended lattice = 2*SS+1
#define WPB 4       // warps (batch elems) per block
#define RD 16       // raw ring rows
#define NEB 4       // em ring rows (slot = row & 3, fixed)
#define NBC (NB*CC) // row stride in floats
#define RAWROW 320  // bytes per raw row (80 floats)
#define EMROW 336   // bytes per em row (84 floats, slot 80 = pad prob 0)

static __device__ __forceinline__ unsigned smem_u32(const void* p) {
    return (unsigned)__cvta_generic_to_shared(p);
}
static __device__ __forceinline__ void cp16(unsigned dst, const float* src) {
    asm volatile("cp.async.cg.shared.global [%0], [%1], 16;\n"
                 :: "r"(dst), "l"(__cvta_generic_to_global(src)) : "memory");
}
static __device__ __forceinline__ void cp_commit() {
    asm volatile("cp.async.commit_group;\n" ::: "memory");
}
template <int N> static __device__ __forceinline__ void cp_wait() {
    asm volatile("cp.async.wait_group %0;\n" :: "n"(N) : "memory");
}
// LDS with compile-time immediate offset: no per-gather IADD
template <int IMM>
static __device__ __forceinline__ float lds_imm(unsigned addr) {
    float v;
    asm volatile("ld.shared.f32 %0, [%1+%2];" : "=f"(v) : "r"(addr), "n"(IMM));
    return v;
}
static __device__ __forceinline__ float lds_reg(unsigned addr) {
    float v;
    asm volatile("ld.shared.f32 %0, [%1];" : "=f"(v) : "r"(addr));
    return v;
}
// exact power of two 2^e, exponent clamped to normal range
static __device__ __forceinline__ float exp2c(int e) {
    e = max(-126, min(127, e));
    return __int_as_float((e + 127) << 23);
}

struct WState {
    float a[9];      // alpha cells (lattice s = lane*9 + j)
    float sk[9];     // skip-transition multiplier (0/1)
    unsigned co[9];  // absolute smem addr of em[0][class] for this cell
    float p8r, p7r;  // boundary alphas shfl'd from lane-1 (pre-rescale snapshot)
    int elane;       // per-lane exponent: true alpha = a * 2^elane
    int eprev;       // lane-1's elane at snapshot time (refreshed EVERY step)
    bool empty;      // lane has no probability mass yet
};

// Core recurrence body given gathered emissions g[9]. Branch-free alignment.
template <bool RESC>
static __device__ __forceinline__ void ctc_core(WState& S, int lane, const float (&g)[9])
{
    // exponent alignment with left neighbor (branch-free; empty lanes adopt)
    int de = S.eprev - S.elane;
    S.elane = S.empty ? S.eprev : S.elane;
    de      = S.empty ? 0 : de;
    float f  = exp2c(de);              // |de| bounded ~40 when non-empty
    float p8 = S.p8r * f, p7 = S.p7r * f;

    // cell updates, descending so in-place reads see old values
#pragma unroll
    for (int j = 8; j >= 2; j--) {
        float tv = S.a[j] + S.a[j - 1];
        tv = fmaf(S.a[j - 2], S.sk[j], tv);
        S.a[j] = tv * g[j];
    }
    { float tv = S.a[1] + S.a[0]; tv = fmaf(p8, S.sk[1], tv); S.a[1] = tv * g[1]; }
    { float tv = S.a[0] + p8;     tv = fmaf(p7, S.sk[0], tv); S.a[0] = tv * g[0]; }

    // injection check (p8 direct, or p7 via skip into cell 0)
    if (p8 > 0.f || p7 * S.sk[0] > 0.f) S.empty = false;

    // boundary snapshot for NEXT step: (pre-rescale values, current exponent)
    S.p8r   = __shfl_up_sync(0xffffffffu, S.a[8], 1);
    S.p7r   = __shfl_up_sync(0xffffffffu, S.a[7], 1);
    S.eprev = __shfl_up_sync(0xffffffffu, S.elane, 1);
    if (lane == 0) { S.p8r = 0.f; S.p7r = 0.f; S.eprev = S.elane; }

    if (RESC) {   // branch-free per-lane power-of-2 renormalization
        float m = fmaxf(fmaxf(fmaxf(S.a[0], S.a[1]), fmaxf(S.a[2], S.a[3])),
                        fmaxf(fmaxf(S.a[4], S.a[5]),
                              fmaxf(fmaxf(S.a[6], S.a[7]), S.a[8])));
        bool nz = m > 0.f;
        int e = nz ? (((__float_as_int(m) >> 23) & 255) - 127) : 0;
        float sc = exp2c(-e);
#pragma unroll
        for (int j = 0; j < 9; j++) S.a[j] *= sc;
        S.elane += e;
        S.empty = !nz;
    }
}

// Step with compile-time em ring slot (gathers use immediate offsets)
template <int SLOT, bool RESC>
static __device__ __forceinline__ void ctc_step(WState& S, int lane)
{
    float g[9];
#pragma unroll
    for (int j = 0; j < 9; j++)
        g[j] = lds_imm<SLOT * EMROW>(S.co[j]);
    ctc_core<RESC>(S, lane, g);
}
// Step with runtime slot (tail only)
static __device__ __forceinline__ void ctc_step_rt(WState& S, int lane, int soff)
{
    float g[9];
#pragma unroll
    for (int j = 0; j < 9; j++)
        g[j] = lds_reg(S.co[j] + (unsigned)soff);
    ctc_core<true>(S, lane, g);
}

static __device__ __forceinline__ float4 exp4(float4 r) {
    float4 p;
    p.x = __expf(r.x); p.y = __expf(r.y); p.z = __expf(r.z); p.w = __expf(r.w);
    return p;
}

__global__ __launch_bounds__(WPB * 32)
void ctc_kernel(const float* __restrict__ lp,   // (T, N, C)
                const int*   __restrict__ tgt,  // (N, S)
                const int*   __restrict__ ilen, // (N,)
                const int*   __restrict__ tlen, // (N,)
                float*       __restrict__ out,  // (N,)
                int nb)
{
    __shared__ __align__(16) float raw[WPB][RD][CC];  // cp.async ring (16 rows)
    __shared__ __align__(16) float em[WPB][NEB][84];  // em ring (slot = row & 3)
    __shared__ int ed[WPB][32];

    const int lane = threadIdx.x & 31;
    const int w    = threadIdx.x >> 5;
    const int n    = blockIdx.x * WPB + w;
    if (n >= nb) return;

    float (&rawW)[RD][CC] = raw[w];
    float (&emW)[NEB][84] = em[w];
    const unsigned rawu  = smem_u32(&rawW[0][0]);          // warp raw base
    const unsigned rawul = rawu + lane * 16;               // + lane slice
    const char*    rawcl = (const char*)&rawW[0][0] + lane * 16;
    const unsigned emu   = smem_u32(&emW[0][0]);

    const int Tn = ilen[n];
    const int tl = tlen[n];

    if (lane < NEB) emW[lane][80] = 0.f;   // pad class -> prob 0 (all 4 slots)

    WState S;
    const int* trow = tgt + (size_t)n * SS;
#pragma unroll
    for (int j = 0; j < 9; j++) {
        int s = lane * 9 + j;
        S.a[j] = 0.f;
        if (s >= LL)            { S.co[j] = emu + 80 * 4; S.sk[j] = 0.f; }
        else if ((s & 1) == 0)  { S.co[j] = emu;          S.sk[j] = 0.f; }  // blank
        else {
            int k = s >> 1;
            int c = trow[k];
            S.co[j] = emu + (unsigned)c * 4;
            S.sk[j] = (k >= 1 && trow[k - 1] != c) ? 1.f : 0.f;
        }
    }

    const float* gbase = lp + (size_t)n * CC;

    // ---- prologue: cp rows 0..15 in 4 groups of 4 ----
#pragma unroll
    for (int gq = 0; gq < 4; gq++) {
        if (lane < 20) {
#pragma unroll
            for (int k = 0; k < 4; k++)
                cp16(rawul + (4 * gq + k) * RAWROW,
                     gbase + (size_t)(4 * gq + k) * NBC + lane * 4);
        }
        cp_commit();
    }
    cp_wait<2>();     // rows 0..7 landed
    __syncwarp();

    // convert rows 0..3 -> em slots 0..3
    if (lane < 20) {
#pragma unroll
        for (int r = 0; r < 4; r++)
            *(float4*)((char*)&emW[r][0] + lane * 16) =
                exp4(*(const float4*)(rawcl + r * RAWROW));
    }
    __syncwarp();

    // alpha init at t=0 from em slot 0
    if (lane == 0) {
        S.a[0] = lds_imm<0>(emu);
        S.a[1] = lds_imm<0>(S.co[1]);
    }
    S.elane = 0;
    S.empty = (lane != 0);
    __syncwarp();

    // convert row 4 -> slot 0 (row 0 no longer needed)
    if (lane < 20)
        *(float4*)((char*)&emW[0][0] + lane * 16) =
            exp4(*(const float4*)(rawcl + 4 * RAWROW));
    __syncwarp();

    // initial boundary snapshot
    S.p8r   = __shfl_up_sync(0xffffffffu, S.a[8], 1);
    S.p7r   = __shfl_up_sync(0xffffffffu, S.a[7], 1);
    S.eprev = __shfl_up_sync(0xffffffffu, S.elane, 1);
    if (lane == 0) { S.p8r = 0.f; S.p7r = 0.f; S.eprev = S.elane; }

    const float* gpre = gbase + (size_t)16 * NBC;   // next prefetch row = 16

    // ---- main loop: 4-step blocks, t = 1, 5, 9, ... (slots 1,2,3,0) ----
    int t = 1;
    for (; t + 3 < Tn; t += 4) {
        cp_wait<1>();   // raw rows <= t+11 landed (need t+4..t+7)

        float4 c0 = make_float4(0.f, 0.f, 0.f, 0.f), c1 = c0, c2 = c0, c3 = c0;
        if (lane < 20) c0 = *(const float4*)(rawcl + ((t + 4) & (RD - 1)) * RAWROW);
        ctc_step<1, false>(S, lane);
        if (lane < 20) {
            *(float4*)((char*)&emW[1][0] + lane * 16) = exp4(c0);   // row t+4
            c1 = *(const float4*)(rawcl + ((t + 5) & (RD - 1)) * RAWROW);
        }
        ctc_step<2, true>(S, lane);
        if (lane < 20) {
            *(float4*)((char*)&emW[2][0] + lane * 16) = exp4(c1);   // row t+5
            c2 = *(const float4*)(rawcl + ((t + 6) & (RD - 1)) * RAWROW);
        }
        ctc_step<3, false>(S, lane);
        if (lane < 20) {
            *(float4*)((char*)&emW[3][0] + lane * 16) = exp4(c2);   // row t+6
            c3 = *(const float4*)(rawcl + ((t + 7) & (RD - 1)) * RAWROW);
        }
        ctc_step<0, true>(S, lane);
        if (lane < 20)
            *(float4*)((char*)&emW[0][0] + lane * 16) = exp4(c3);   // row t+7

        // prefetch rows t+15..t+18 (one group)
        if (lane < 20) {
#pragma unroll
            for (int k = 0; k < 4; k++) {
                int row = t + 15 + k;
                if (row < TT)
                    cp16(rawul + (row & (RD - 1)) * RAWROW,
                         gpre + (size_t)k * NBC + lane * 4);
            }
        }
        cp_commit();
        gpre += (size_t)4 * NBC;
        __syncwarp();
    }

    // ---- tail: 0..3 remaining steps (em rows already converted) ----
    for (; t < Tn; t++)
        ctc_step_rt(S, lane, (t & 3) * EMROW);

    // ---- finalize ----
    cp_wait<0>();
    __syncwarp();
    float* dump = &rawW[0][0];
#pragma unroll
    for (int j = 0; j < 9; j++)
        dump[lane * 9 + j] = S.a[j];
    ed[w][lane] = S.elane;
    __syncwarp();
    if (lane == 0) {
        int s1 = 2 * tl, s2 = 2 * tl - 1;
        float va = dump[s1]; int ea = ed[w][s1 / 9];
        float vb = dump[s2]; int eb = ed[w][s2 / 9];
        int emax = max(ea, eb);
        float v = va * exp2c(ea - emax) + vb * exp2c(eb - emax);
        float loss = -((__log2f(v) + (float)emax) * 0.69314718055994530942f);
        if (!isfinite(loss) || !(loss < 1e10f)) loss = 0.f;  // zero_infinity
        out[n] = loss;
    }
}

extern "C" void kernel_launch(void* const* d_in, const int* in_sizes, int n_in,
                              void* d_out, int out_size) {
    const float* lp   = (const float*)d_in[0];
    const int*   tgt  = (const int*)d_in[1];
    const int*   ilen = (const int*)d_in[2];
    const int*   tlen = (const int*)d_in[3];
    float*       out  = (float*)d_out;
    int nb = out_size;                 // N
    int blocks = (nb + WPB - 1) / WPB; // 128
    ctc_kernel<<<blocks, WPB * 32>>>(lp, tgt, ilen, tlen, out, nb);
}

// round 13
// speedup vs baseline: 1.6221x; 1.1830x over previous
#include <cuda_runtime.h>
#include <cstdint>

#define TT 512      // time steps
#define NB 512      // batch
#define CC 80       // classes
#define SS 128      // max target len
#define LL 257      // extended lattice = 2*SS+1
#define WPB 4       // warps (batch elems) per block
#define NBC (NB*CC) // row stride in floats
#define EMROW 336   // bytes per em slot (84 floats; 80 used, 4 pad for bank spread)

static __device__ __forceinline__ unsigned smem_u32(const void* p) {
    return (unsigned)__cvta_generic_to_shared(p);
}
template <int IMM>
static __device__ __forceinline__ float lds_imm(unsigned addr) {
    float v;
    asm volatile("ld.shared.f32 %0, [%1+%2];" : "=f"(v) : "r"(addr), "n"(IMM));
    return v;
}
static __device__ __forceinline__ float lds_reg(unsigned addr) {
    float v;
    asm volatile("ld.shared.f32 %0, [%1];" : "=f"(v) : "r"(addr));
    return v;
}
// exact power of two 2^e, exponent clamped to normal range
static __device__ __forceinline__ float exp2c(int e) {
    e = max(-126, min(127, e));
    return __int_as_float((e + 127) << 23);
}
static __device__ __forceinline__ float4 exp4(float4 r) {
    float4 p;
    p.x = __expf(r.x); p.y = __expf(r.y); p.z = __expf(r.z); p.w = __expf(r.w);
    return p;
}

struct WState {
    float a[9];      // cells s = 8*lane + j (j=0..7); a[8] = cell 256, lane 31 only
    float sk[4];     // skip multiplier for label cells j=1,3,5,7
    unsigned coL[4]; // smem addr (slot 0) of label emission for j=1,3,5,7
    unsigned emu;    // smem addr (slot 0) of blank emission (class 0)
    float m31;       // 1.0 on lane 31, else 0 (gates cell 256)
    float pAr;       // boundary alpha a[7] from lane-1 (pre-rescale snapshot)
    int elane;       // per-lane exponent: true alpha = a * 2^elane
    int eprev;       // lane-1's elane at snapshot time
    bool empty;      // lane has no probability mass yet
};

template <bool RESC>
static __device__ __forceinline__ void ctc_core(
    WState& S, int lane, float gb, float g0, float g1, float g2, float g3)
{
    // exponent alignment with left neighbor (branch-free; empty lanes adopt)
    int de = S.eprev - S.elane;
    S.elane = S.empty ? S.eprev : S.elane;
    de      = S.empty ? 0 : de;
    float f  = exp2c(de);
    float pA = S.pAr * f;

    // descending update: old values read before overwrite
    S.a[8] = fmaf(S.m31, S.a[7], S.a[8]) * gb;                              // s=256 (blank, lane31)
    { float tv = S.a[7] + S.a[6]; tv = fmaf(S.a[5], S.sk[3], tv); S.a[7] = tv * g3; }
    S.a[6] = (S.a[6] + S.a[5]) * gb;                                        // blank: no skip
    { float tv = S.a[5] + S.a[4]; tv = fmaf(S.a[3], S.sk[2], tv); S.a[5] = tv * g2; }
    S.a[4] = (S.a[4] + S.a[3]) * gb;
    { float tv = S.a[3] + S.a[2]; tv = fmaf(S.a[1], S.sk[1], tv); S.a[3] = tv * g1; }
    S.a[2] = (S.a[2] + S.a[1]) * gb;
    { float tv = S.a[1] + S.a[0]; tv = fmaf(pA,     S.sk[0], tv); S.a[1] = tv * g0; }
    S.a[0] = (S.a[0] + pA) * gb;

    if (pA > 0.f) S.empty = false;   // only entry point for new mass

    // boundary snapshot for NEXT step (pre-rescale value + current exponent)
    S.pAr   = __shfl_up_sync(0xffffffffu, S.a[7], 1);
    S.eprev = __shfl_up_sync(0xffffffffu, S.elane, 1);
    if (lane == 0) { S.pAr = 0.f; S.eprev = S.elane; }

    if (RESC) {   // branch-free per-lane power-of-2 renormalization
        float m = fmaxf(fmaxf(fmaxf(S.a[0], S.a[1]), fmaxf(S.a[2], S.a[3])),
                        fmaxf(fmaxf(S.a[4], S.a[5]),
                              fmaxf(fmaxf(S.a[6], S.a[7]), S.a[8])));
        bool nz = m > 0.f;
        int e = nz ? (((__float_as_int(m) >> 23) & 255) - 127) : 0;
        float sc = exp2c(-e);
#pragma unroll
        for (int j = 0; j < 9; j++) S.a[j] *= sc;
        S.elane += e;
        S.empty = !nz;
    }
}

template <int SLOT, bool RESC>
static __device__ __forceinline__ void ctc_step(WState& S, int lane)
{
    float gb = lds_imm<SLOT * EMROW>(S.emu);
    float g0 = lds_imm<SLOT * EMROW>(S.coL[0]);
    float g1 = lds_imm<SLOT * EMROW>(S.coL[1]);
    float g2 = lds_imm<SLOT * EMROW>(S.coL[2]);
    float g3 = lds_imm<SLOT * EMROW>(S.coL[3]);
    ctc_core<RESC>(S, lane, gb, g0, g1, g2, g3);
}
static __device__ __forceinline__ void ctc_step_rt(WState& S, int lane, unsigned off)
{
    float gb = lds_reg(S.emu + off);
    float g0 = lds_reg(S.coL[0] + off);
    float g1 = lds_reg(S.coL[1] + off);
    float g2 = lds_reg(S.coL[2] + off);
    float g3 = lds_reg(S.coL[3] + off);
    ctc_core<true>(S, lane, gb, g0, g1, g2, g3);
}

// One 4-step block: steps tb..tb+3 (slots 1,2,3,0), convert Q (rows tb+4..tb+7),
// refill Q with rows tb+12..tb+15.
static __device__ __forceinline__ void block4(
    WState& S, int lane, char* emb, float4 (&Q)[4], const float* gQ, int tb)
{
    const bool ld = lane < 20;
    ctc_step<1, false>(S, lane);
    if (ld) *(float4*)(emb + 1 * EMROW) = exp4(Q[0]);
    ctc_step<2, true >(S, lane);
    if (ld) *(float4*)(emb + 2 * EMROW) = exp4(Q[1]);
    ctc_step<3, false>(S, lane);
    if (ld) *(float4*)(emb + 3 * EMROW) = exp4(Q[2]);
    ctc_step<0, true >(S, lane);
    if (ld) {
        *(float4*)(emb + 0 * EMROW) = exp4(Q[3]);
#pragma unroll
        for (int k = 0; k < 4; k++)
            if (tb + 12 + k < TT)
                Q[k] = *(const float4*)(gQ + (size_t)k * NBC);
    }
    __syncwarp();
}

__global__ __launch_bounds__(WPB * 32)
void ctc_kernel(const float* __restrict__ lp,   // (T, N, C)
                const int*   __restrict__ tgt,  // (N, S)
                const int*   __restrict__ ilen, // (N,)
                const int*   __restrict__ tlen, // (N,)
                float*       __restrict__ out,  // (N,)
                int nb)
{
    __shared__ __align__(16) float em[WPB][4][84];  // em ring (slot = row & 3)
    __shared__ float dmp[WPB][264];                 // finalize dump (257 cells)
    __shared__ int ed[WPB][32];                     // per-lane exponents

    const int lane = threadIdx.x & 31;
    const int w    = threadIdx.x >> 5;
    const int n    = blockIdx.x * WPB + w;
    if (n >= nb) return;

    char* emb = (char*)&em[w][0][0] + lane * 16;    // this lane's convert slice
    const unsigned emu = smem_u32(&em[w][0][0]);

    const int Tn = ilen[n];
    const int tl = tlen[n];

    WState S;
    S.emu = emu;
    S.m31 = (lane == 31) ? 1.f : 0.f;
    const int* trow = tgt + (size_t)n * SS;
#pragma unroll
    for (int j = 0; j < 9; j++) S.a[j] = 0.f;
#pragma unroll
    for (int jj = 0; jj < 4; jj++) {          // label cells j = 2*jj+1, s = 8*lane+j
        int k = 4 * lane + jj;                // label index, always < 128
        int c = trow[k];
        S.coL[jj] = emu + (unsigned)c * 4;
        S.sk[jj]  = (k >= 1 && trow[k - 1] != c) ? 1.f : 0.f;
    }

    const float* glane = lp + (size_t)n * CC + lane * 4;

    // ---- prologue: LDG rows 0..8, convert rows 0..4 ----
    float4 r0 = make_float4(0.f, 0.f, 0.f, 0.f);
    float4 qa[4] = {r0, r0, r0, r0}, qb[4] = {r0, r0, r0, r0};
    if (lane < 20) {
        r0 = *(const float4*)(glane);
#pragma unroll
        for (int k = 0; k < 4; k++) qa[k] = *(const float4*)(glane + (size_t)(1 + k) * NBC);
#pragma unroll
        for (int k = 0; k < 4; k++) qb[k] = *(const float4*)(glane + (size_t)(5 + k) * NBC);
    }
    if (lane < 20) *(float4*)(emb + 0 * EMROW) = exp4(r0);      // row 0 -> slot 0
    __syncwarp();

    // alpha at t=0: lattice positions 0 (blank) and 1 (first label), lane 0
    if (lane == 0) {
        S.a[0] = lds_reg(S.emu);
        S.a[1] = lds_reg(S.coL[0]);
    }
    if (lane < 20) {                                            // rows 1..3 -> slots 1..3
        *(float4*)(emb + 1 * EMROW) = exp4(qa[0]);
        *(float4*)(emb + 2 * EMROW) = exp4(qa[1]);
        *(float4*)(emb + 3 * EMROW) = exp4(qa[2]);
    }
    __syncwarp();   // init read of slot 0 done before row-4 overwrite
    if (lane < 20) {
        *(float4*)(emb + 0 * EMROW) = exp4(qa[3]);              // row 4 -> slot 0
#pragma unroll
        for (int k = 0; k < 4; k++) qa[k] = *(const float4*)(glane + (size_t)(9 + k) * NBC);
    }
    S.elane = 0;
    S.empty = (lane != 0);
    S.pAr   = __shfl_up_sync(0xffffffffu, S.a[7], 1);
    S.eprev = __shfl_up_sync(0xffffffffu, S.elane, 1);
    if (lane == 0) { S.pAr = 0.f; S.eprev = S.elane; }
    __syncwarp();

    // ---- main loop: double 4-step blocks (qb then qa) ----
    int t = 1;
    for (; t + 7 < Tn; t += 8) {
        block4(S, lane, emb, qb, glane + (size_t)(t + 12) * NBC, t);
        block4(S, lane, emb, qa, glane + (size_t)(t + 16) * NBC, t + 4);
    }
    if (t + 3 < Tn) {
        block4(S, lane, emb, qb, glane + (size_t)(t + 12) * NBC, t);
        t += 4;
    }
    // tail: <=3 steps, em rows t..t+3 already converted by the last block
    for (; t < Tn; t++)
        ctc_step_rt(S, lane, (unsigned)((t & 3) * EMROW));

    // ---- finalize ----
    __syncwarp();
#pragma unroll
    for (int j = 0; j < 8; j++)
        dmp[w][8 * lane + j] = S.a[j];
    if (lane == 31) dmp[w][256] = S.a[8];
    ed[w][lane] = S.elane;
    __syncwarp();
    if (lane == 0) {
        int s1 = 2 * tl, s2 = s1 - 1;
        float va = dmp[w][s1]; int ea = ed[w][min(s1 >> 3, 31)];
        float vb = dmp[w][s2]; int eb = ed[w][s2 >> 3];
        int emax = max(ea, eb);
        float v = va * exp2c(ea - emax) + vb * exp2c(eb - emax);
        float loss = -((__log2f(v) + (float)emax) * 0.69314718055994530942f);
        if (!isfinite(loss) || !(loss < 1e10f)) loss = 0.f;  // zero_infinity
        out[n] = loss;
    }
}

extern "C" void kernel_launch(void* const* d_in, const int* in_sizes, int n_in,
                              void* d_out, int out_size) {
    const float* lp   = (const float*)d_in[0];
    const int*   tgt  = (const int*)d_in[1];
    const int*   ilen = (const int*)d_in[2];
    const int*   tlen = (const int*)d_in[3];
    float*       out  = (float*)d_out;
    int nb = out_size;                 // N
    int blocks = (nb + WPB - 1) / WPB; // 128
    ctc_kernel<<<blocks, WPB * 32>>>(lp, tgt, ilen, tlen, out, nb);
}